// round 9
// baseline (speedup 1.0000x reference)
#include <cuda_runtime.h>
#include <cstdint>

// Geometric product in Cl(3,0,1): out[n,k] = sum_{i,j} a[n,i] b[n,j] C[i,j,k]
// Structure constants baked in at compile time (metric = 1,1,1,0).
//
// R9: persistent CTAs + double-buffered cp.async prefetch. Each CTA loops
// over 128-row tiles with stride gridDim; while computing tile i it already
// has tile i+stride's loads in flight (cp.async into the other buffer).
// Removes launch-wave transitions (1036 resident CTAs, no further waves)
// and keeps every CTA contributing load MLP continuously.
// Outputs go straight from registers via streaming STG.128 (__stcs).

static __host__ __device__ constexpr int cayley_sign(int A, int B) {
    if (A & B & 8) return 0;            // degenerate generator e3 (metric 0)
    int s = 0;
    int sa = A >> 1;
    while (sa) {
        int x = sa & B;
        while (x) { s += 1; x &= (x - 1); }
        sa >>= 1;
    }
    return (s & 1) ? -1 : 1;
}

// Swizzle within a 512-float4 (128-row) tile: r=idx>>2, c=idx&3,
// pos = 4r | (c ^ ((r>>1)&3)). Conflict-free for unit-stride staging
// and for per-row quad reads in permuted order.
static __device__ __forceinline__ int swz(int idx) {
    const int r = idx >> 2;
    const int c = idx & 3;
    return (r << 2) | (c ^ ((r >> 1) & 3));
}

static __device__ __forceinline__ uint32_t smem_u32(const void* p) {
    return (uint32_t)__cvta_generic_to_shared(p);
}

static __device__ __forceinline__ void cp_async16(uint32_t dst, const void* src) {
    asm volatile("cp.async.cg.shared.global [%0], [%1], 16;"
                 :: "r"(dst), "l"(src) : "memory");
}

static constexpr int TPB       = 128;   // threads per CTA = rows per tile
static constexpr int TILE_F4   = TPB * 4;

__global__ void __launch_bounds__(TPB)
gp_kernel(const float4* __restrict__ a4,
          const float4* __restrict__ b4,
          float4* __restrict__ o4,
          int n_rows, int n_tiles) {
    __shared__ __align__(16) float4 sa[2][TILE_F4];   // 2 x 8 KB
    __shared__ __align__(16) float4 sb[2][TILE_F4];   // 2 x 8 KB

    const int t      = threadIdx.x;
    const int stride = gridDim.x;
    const int n4     = n_rows * 4;

    // ---- Prologue: issue loads for first tile into buffer 0 ----
    int tile = blockIdx.x;
    {
        const int base4 = tile * TILE_F4;
        #pragma unroll
        for (int v = 0; v < 4; ++v) {
            const int idx = v * TPB + t;
            if (base4 + idx < n4) {
                cp_async16(smem_u32(&sa[0][swz(idx)]), &a4[base4 + idx]);
                cp_async16(smem_u32(&sb[0][swz(idx)]), &b4[base4 + idx]);
            }
        }
        asm volatile("cp.async.commit_group;" ::: "memory");
    }

    int p = 0;
    for (; tile < n_tiles; tile += stride, p ^= 1) {
        // ---- Prefetch next tile into the other buffer ----
        const int next = tile + stride;
        if (next < n_tiles) {
            const int nb4 = next * TILE_F4;
            #pragma unroll
            for (int v = 0; v < 4; ++v) {
                const int idx = v * TPB + t;
                if (nb4 + idx < n4) {
                    cp_async16(smem_u32(&sa[p ^ 1][swz(idx)]), &a4[nb4 + idx]);
                    cp_async16(smem_u32(&sb[p ^ 1][swz(idx)]), &b4[nb4 + idx]);
                }
            }
        }
        asm volatile("cp.async.commit_group;" ::: "memory");
        // Wait until only the just-committed group is pending -> current ready
        asm volatile("cp.async.wait_group 1;" ::: "memory");
        __syncthreads();

        // ---- Read own row (conflict-free via swizzle) ----
        float a[16], b[16];
        const int s = (t >> 1) & 3;
        #pragma unroll
        for (int v = 0; v < 4; ++v) {
            const int u = v ^ s;
            const float4 va = sa[p][(t << 2) | u];
            const float4 vb = sb[p][(t << 2) | u];
            a[v * 4 + 0] = va.x; a[v * 4 + 1] = va.y;
            a[v * 4 + 2] = va.z; a[v * 4 + 3] = va.w;
            b[v * 4 + 0] = vb.x; b[v * 4 + 1] = vb.y;
            b[v * 4 + 2] = vb.z; b[v * 4 + 3] = vb.w;
        }

        // ---- 192 straight-line FFMAs ----
        float c[16];
        #pragma unroll
        for (int k = 0; k < 16; ++k) c[k] = 0.0f;
        #pragma unroll
        for (int A = 0; A < 16; ++A) {
            #pragma unroll
            for (int B = 0; B < 16; ++B) {
                const int sg = cayley_sign(A, B);
                if (sg == 1)       c[A ^ B] = fmaf( a[A], b[B], c[A ^ B]);
                else if (sg == -1) c[A ^ B] = fmaf(-a[A], b[B], c[A ^ B]);
            }
        }

        // ---- Direct streaming stores from registers ----
        const int row = tile * TPB + t;
        if (row < n_rows) {
            const size_t ro = (size_t)row * 4;
            __stcs(&o4[ro + 0], make_float4(c[0],  c[1],  c[2],  c[3]));
            __stcs(&o4[ro + 1], make_float4(c[4],  c[5],  c[6],  c[7]));
            __stcs(&o4[ro + 2], make_float4(c[8],  c[9],  c[10], c[11]));
            __stcs(&o4[ro + 3], make_float4(c[12], c[13], c[14], c[15]));
        }

        // All threads done reading buffer p before next iteration issues
        // cp.async into it (next iteration's "other" buffer is p).
        __syncthreads();
    }
}

extern "C" void kernel_launch(void* const* d_in, const int* in_sizes, int n_in,
                              void* d_out, int out_size) {
    const float4* a4 = (const float4*)d_in[0];
    const float4* b4 = (const float4*)d_in[1];
    // d_in[2] is the Cayley tensor; values are baked in at compile time.
    float4* o4 = (float4*)d_out;

    const int n_rows  = in_sizes[0] / 16;
    const int n_tiles = (n_rows + TPB - 1) / TPB;

    // Persistent grid: 7 CTAs/SM (32 KB smem each) x 148 SMs.
    int grid = 148 * 7;
    if (grid > n_tiles) grid = n_tiles;

    gp_kernel<<<grid, TPB>>>(a4, b4, o4, n_rows, n_tiles);
}

// round 10
// speedup vs baseline: 1.1492x; 1.1492x over previous
#include <cuda_runtime.h>
#include <cstdint>

// Geometric product in Cl(3,0,1): out[n,k] = sum_{i,j} a[n,i] b[n,j] C[i,j,k]
// Structure constants baked in at compile time (metric = 1,1,1,0).
//
// R10 (final) = R6 skeleton — the best-measured variant (DRAM 76.8%,
// ncu 58.5us) — plus streaming (evict-first) hints on the output stores.
// Structure: cp.async.cg staged inputs (L2->smem direct, no L1/RF round
// trip), XOR-swizzled smem (all LDS/STS conflict-free), register-resident
// 192-FFMA constant-folded product, smem-gathered unit-stride STG.128
// with __stcs so the write stream doesn't displace inbound read sectors
// in L2. Three structurally different variants (R2/R6/R7) all plateau at
// ~6.2 TB/s: this is the chip's mixed 2:1 read/write ceiling, which this
// kernel saturates.

static __host__ __device__ constexpr int cayley_sign(int A, int B) {
    if (A & B & 8) return 0;            // degenerate generator e3 (metric 0)
    int s = 0;
    int sa = A >> 1;
    while (sa) {
        int x = sa & B;
        while (x) { s += 1; x &= (x - 1); }
        sa >>= 1;
    }
    return (s & 1) ? -1 : 1;
}

// Swizzled position for flat float4 index idx within a 1024-float4 tile:
//   r = idx>>2 (row), c = idx&3 (quad); pos = 4r | (c ^ ((r>>1)&3))
// Conflict-free for both unit-stride staging and per-row access.
static __device__ __forceinline__ int swz(int idx) {
    const int r = idx >> 2;
    const int c = idx & 3;
    return (r << 2) | (c ^ ((r >> 1) & 3));
}

static __device__ __forceinline__ uint32_t smem_u32(const void* p) {
    return (uint32_t)__cvta_generic_to_shared(p);
}

static __device__ __forceinline__ void cp_async16(uint32_t dst, const void* src) {
    asm volatile("cp.async.cg.shared.global [%0], [%1], 16;"
                 :: "r"(dst), "l"(src) : "memory");
}

__global__ void __launch_bounds__(256)
gp_kernel(const float4* __restrict__ a4,
          const float4* __restrict__ b4,
          float4* __restrict__ o4,
          int n_rows) {
    __shared__ __align__(16) float4 sa[1024];   // 16 KB, reused for output
    __shared__ __align__(16) float4 sb[1024];   // 16 KB

    const int t     = threadIdx.x;
    const int base4 = blockIdx.x * 1024;
    const int row0  = blockIdx.x * 256;
    const bool full_tile = (row0 + 256 <= n_rows);

    // ---- Stage a and b: cp.async unit-stride gmem -> swizzled smem ----
    if (full_tile) {
        #pragma unroll
        for (int v = 0; v < 4; ++v) {
            const int idx = v * 256 + t;
            cp_async16(smem_u32(&sa[swz(idx)]), &a4[base4 + idx]);
            cp_async16(smem_u32(&sb[swz(idx)]), &b4[base4 + idx]);
        }
    } else {
        #pragma unroll
        for (int v = 0; v < 4; ++v) {
            const int idx = v * 256 + t;
            const int pos = swz(idx);
            if ((base4 + idx) < n_rows * 4) {
                cp_async16(smem_u32(&sa[pos]), &a4[base4 + idx]);
                cp_async16(smem_u32(&sb[pos]), &b4[base4 + idx]);
            } else {
                sa[pos] = make_float4(0.f, 0.f, 0.f, 0.f);
                sb[pos] = make_float4(0.f, 0.f, 0.f, 0.f);
            }
        }
    }
    asm volatile("cp.async.commit_group;" ::: "memory");
    asm volatile("cp.async.wait_group 0;" ::: "memory");
    __syncthreads();

    // ---- Each thread reads its own row (conflict-free via swizzle) ----
    float a[16], b[16];
    const int s = (t >> 1) & 3;
    #pragma unroll
    for (int v = 0; v < 4; ++v) {
        const int u = v ^ s;                       // physical quad holding logical quad v
        const float4 va = sa[(t << 2) | u];
        const float4 vb = sb[(t << 2) | u];
        a[v * 4 + 0] = va.x; a[v * 4 + 1] = va.y;
        a[v * 4 + 2] = va.z; a[v * 4 + 3] = va.w;
        b[v * 4 + 0] = vb.x; b[v * 4 + 1] = vb.y;
        b[v * 4 + 2] = vb.z; b[v * 4 + 3] = vb.w;
    }

    // ---- 192 straight-line FFMAs ----
    float c[16];
    #pragma unroll
    for (int k = 0; k < 16; ++k) c[k] = 0.0f;

    #pragma unroll
    for (int A = 0; A < 16; ++A) {
        #pragma unroll
        for (int B = 0; B < 16; ++B) {
            const int sg = cayley_sign(A, B);
            if (sg == 1) {
                c[A ^ B] = fmaf(a[A], b[B], c[A ^ B]);
            } else if (sg == -1) {
                c[A ^ B] = fmaf(-a[A], b[B], c[A ^ B]);
            }
        }
    }

    // ---- Write own output row into sa (own region; no pre-sync needed) ----
    #pragma unroll
    for (int v = 0; v < 4; ++v) {
        const int u = v ^ s;
        sa[(t << 2) | u] = make_float4(c[v * 4 + 0], c[v * 4 + 1],
                                       c[v * 4 + 2], c[v * 4 + 3]);
    }
    __syncthreads();

    // ---- Gather + unit-stride streaming global stores (evict-first) ----
    if (full_tile) {
        #pragma unroll
        for (int v = 0; v < 4; ++v) {
            const int idx = v * 256 + t;
            __stcs(&o4[base4 + idx], sa[swz(idx)]);
        }
    } else {
        #pragma unroll
        for (int v = 0; v < 4; ++v) {
            const int idx = v * 256 + t;
            if ((base4 + idx) < n_rows * 4)
                __stcs(&o4[base4 + idx], sa[swz(idx)]);
        }
    }
}

extern "C" void kernel_launch(void* const* d_in, const int* in_sizes, int n_in,
                              void* d_out, int out_size) {
    const float4* a4 = (const float4*)d_in[0];
    const float4* b4 = (const float4*)d_in[1];
    // d_in[2] is the Cayley tensor; values are baked in at compile time.
    float4* o4 = (float4*)d_out;

    const int n_rows = in_sizes[0] / 16;
    const int blocks = (n_rows + 255) / 256;
    gp_kernel<<<blocks, 256>>>(a4, b4, o4, n_rows);
}

// round 11
// speedup vs baseline: 1.1544x; 1.0046x over previous
#include <cuda_runtime.h>
#include <cstdint>

// Geometric product in Cl(3,0,1): out[n,k] = sum_{i,j} a[n,i] b[n,j] C[i,j,k]
// Structure constants baked in at compile time (metric = 1,1,1,0).
//
// R11 = R10 (best variant: cp.async staged inputs, XOR-swizzled smem,
// 192-FFMA constant-folded product, unit-stride __stcs output) with the
// read stream additionally tagged L2::evict_first via an access policy:
// inputs are single-use, so their lines should die early in L2 instead of
// competing with the write-allocated output stream. Four structural
// variants plateau at ~6.2 TB/s (78% of spec) — the chip's mixed 2:1
// read/write ceiling; this kernel saturates it.

static __host__ __device__ constexpr int cayley_sign(int A, int B) {
    if (A & B & 8) return 0;            // degenerate generator e3 (metric 0)
    int s = 0;
    int sa = A >> 1;
    while (sa) {
        int x = sa & B;
        while (x) { s += 1; x &= (x - 1); }
        sa >>= 1;
    }
    return (s & 1) ? -1 : 1;
}

// Swizzled position for flat float4 index idx within a 1024-float4 tile:
//   r = idx>>2 (row), c = idx&3 (quad); pos = 4r | (c ^ ((r>>1)&3))
// Conflict-free for both unit-stride staging and per-row access.
static __device__ __forceinline__ int swz(int idx) {
    const int r = idx >> 2;
    const int c = idx & 3;
    return (r << 2) | (c ^ ((r >> 1) & 3));
}

static __device__ __forceinline__ uint32_t smem_u32(const void* p) {
    return (uint32_t)__cvta_generic_to_shared(p);
}

static __device__ __forceinline__ uint64_t evict_first_policy() {
    uint64_t pol;
    asm("createpolicy.fractional.L2::evict_first.b64 %0, 1.0;" : "=l"(pol));
    return pol;
}

static __device__ __forceinline__ void cp_async16_ef(uint32_t dst, const void* src,
                                                     uint64_t pol) {
    asm volatile("cp.async.cg.shared.global.L2::cache_hint [%0], [%1], 16, %2;"
                 :: "r"(dst), "l"(src), "l"(pol) : "memory");
}

__global__ void __launch_bounds__(256)
gp_kernel(const float4* __restrict__ a4,
          const float4* __restrict__ b4,
          float4* __restrict__ o4,
          int n_rows) {
    __shared__ __align__(16) float4 sa[1024];   // 16 KB, reused for output
    __shared__ __align__(16) float4 sb[1024];   // 16 KB

    const int t     = threadIdx.x;
    const int base4 = blockIdx.x * 1024;
    const int row0  = blockIdx.x * 256;
    const bool full_tile = (row0 + 256 <= n_rows);
    const uint64_t pol = evict_first_policy();

    // ---- Stage a and b: cp.async (L2 evict-first) gmem -> swizzled smem ----
    if (full_tile) {
        #pragma unroll
        for (int v = 0; v < 4; ++v) {
            const int idx = v * 256 + t;
            cp_async16_ef(smem_u32(&sa[swz(idx)]), &a4[base4 + idx], pol);
            cp_async16_ef(smem_u32(&sb[swz(idx)]), &b4[base4 + idx], pol);
        }
    } else {
        #pragma unroll
        for (int v = 0; v < 4; ++v) {
            const int idx = v * 256 + t;
            const int pos = swz(idx);
            if ((base4 + idx) < n_rows * 4) {
                cp_async16_ef(smem_u32(&sa[pos]), &a4[base4 + idx], pol);
                cp_async16_ef(smem_u32(&sb[pos]), &b4[base4 + idx], pol);
            } else {
                sa[pos] = make_float4(0.f, 0.f, 0.f, 0.f);
                sb[pos] = make_float4(0.f, 0.f, 0.f, 0.f);
            }
        }
    }
    asm volatile("cp.async.commit_group;" ::: "memory");
    asm volatile("cp.async.wait_group 0;" ::: "memory");
    __syncthreads();

    // ---- Each thread reads its own row (conflict-free via swizzle) ----
    float a[16], b[16];
    const int s = (t >> 1) & 3;
    #pragma unroll
    for (int v = 0; v < 4; ++v) {
        const int u = v ^ s;                       // physical quad holding logical quad v
        const float4 va = sa[(t << 2) | u];
        const float4 vb = sb[(t << 2) | u];
        a[v * 4 + 0] = va.x; a[v * 4 + 1] = va.y;
        a[v * 4 + 2] = va.z; a[v * 4 + 3] = va.w;
        b[v * 4 + 0] = vb.x; b[v * 4 + 1] = vb.y;
        b[v * 4 + 2] = vb.z; b[v * 4 + 3] = vb.w;
    }

    // ---- 192 straight-line FFMAs ----
    float c[16];
    #pragma unroll
    for (int k = 0; k < 16; ++k) c[k] = 0.0f;

    #pragma unroll
    for (int A = 0; A < 16; ++A) {
        #pragma unroll
        for (int B = 0; B < 16; ++B) {
            const int sg = cayley_sign(A, B);
            if (sg == 1) {
                c[A ^ B] = fmaf(a[A], b[B], c[A ^ B]);
            } else if (sg == -1) {
                c[A ^ B] = fmaf(-a[A], b[B], c[A ^ B]);
            }
        }
    }

    // ---- Write own output row into sa (own region; no pre-sync needed) ----
    #pragma unroll
    for (int v = 0; v < 4; ++v) {
        const int u = v ^ s;
        sa[(t << 2) | u] = make_float4(c[v * 4 + 0], c[v * 4 + 1],
                                       c[v * 4 + 2], c[v * 4 + 3]);
    }
    __syncthreads();

    // ---- Gather + unit-stride streaming global stores (evict-first) ----
    if (full_tile) {
        #pragma unroll
        for (int v = 0; v < 4; ++v) {
            const int idx = v * 256 + t;
            __stcs(&o4[base4 + idx], sa[swz(idx)]);
        }
    } else {
        #pragma unroll
        for (int v = 0; v < 4; ++v) {
            const int idx = v * 256 + t;
            if ((base4 + idx) < n_rows * 4)
                __stcs(&o4[base4 + idx], sa[swz(idx)]);
        }
    }
}

extern "C" void kernel_launch(void* const* d_in, const int* in_sizes, int n_in,
                              void* d_out, int out_size) {
    const float4* a4 = (const float4*)d_in[0];
    const float4* b4 = (const float4*)d_in[1];
    // d_in[2] is the Cayley tensor; values are baked in at compile time.
    float4* o4 = (float4*)d_out;

    const int n_rows = in_sizes[0] / 16;
    const int blocks = (n_rows + 255) / 256;
    gp_kernel<<<blocks, 256>>>(a4, b4, o4, n_rows);
}

// round 12
// speedup vs baseline: 1.1556x; 1.0010x over previous
#include <cuda_runtime.h>
#include <cstdint>

// Geometric product in Cl(3,0,1): out[n,k] = sum_{i,j} a[n,i] b[n,j] C[i,j,k]
// Structure constants baked in at compile time (metric = 1,1,1,0).
//
// R11 = R10 (best variant: cp.async staged inputs, XOR-swizzled smem,
// 192-FFMA constant-folded product, unit-stride __stcs output) with the
// read stream additionally tagged L2::evict_first via an access policy:
// inputs are single-use, so their lines should die early in L2 instead of
// competing with the write-allocated output stream. Four structural
// variants plateau at ~6.2 TB/s (78% of spec) — the chip's mixed 2:1
// read/write ceiling; this kernel saturates it.

static __host__ __device__ constexpr int cayley_sign(int A, int B) {
    if (A & B & 8) return 0;            // degenerate generator e3 (metric 0)
    int s = 0;
    int sa = A >> 1;
    while (sa) {
        int x = sa & B;
        while (x) { s += 1; x &= (x - 1); }
        sa >>= 1;
    }
    return (s & 1) ? -1 : 1;
}

// Swizzled position for flat float4 index idx within a 1024-float4 tile:
//   r = idx>>2 (row), c = idx&3 (quad); pos = 4r | (c ^ ((r>>1)&3))
// Conflict-free for both unit-stride staging and per-row access.
static __device__ __forceinline__ int swz(int idx) {
    const int r = idx >> 2;
    const int c = idx & 3;
    return (r << 2) | (c ^ ((r >> 1) & 3));
}

static __device__ __forceinline__ uint32_t smem_u32(const void* p) {
    return (uint32_t)__cvta_generic_to_shared(p);
}

static __device__ __forceinline__ uint64_t evict_first_policy() {
    uint64_t pol;
    asm("createpolicy.fractional.L2::evict_first.b64 %0, 1.0;" : "=l"(pol));
    return pol;
}

static __device__ __forceinline__ void cp_async16_ef(uint32_t dst, const void* src,
                                                     uint64_t pol) {
    asm volatile("cp.async.cg.shared.global.L2::cache_hint [%0], [%1], 16, %2;"
                 :: "r"(dst), "l"(src), "l"(pol) : "memory");
}

__global__ void __launch_bounds__(256)
gp_kernel(const float4* __restrict__ a4,
          const float4* __restrict__ b4,
          float4* __restrict__ o4,
          int n_rows) {
    __shared__ __align__(16) float4 sa[1024];   // 16 KB, reused for output
    __shared__ __align__(16) float4 sb[1024];   // 16 KB

    const int t     = threadIdx.x;
    const int base4 = blockIdx.x * 1024;
    const int row0  = blockIdx.x * 256;
    const bool full_tile = (row0 + 256 <= n_rows);
    const uint64_t pol = evict_first_policy();

    // ---- Stage a and b: cp.async (L2 evict-first) gmem -> swizzled smem ----
    if (full_tile) {
        #pragma unroll
        for (int v = 0; v < 4; ++v) {
            const int idx = v * 256 + t;
            cp_async16_ef(smem_u32(&sa[swz(idx)]), &a4[base4 + idx], pol);
            cp_async16_ef(smem_u32(&sb[swz(idx)]), &b4[base4 + idx], pol);
        }
    } else {
        #pragma unroll
        for (int v = 0; v < 4; ++v) {
            const int idx = v * 256 + t;
            const int pos = swz(idx);
            if ((base4 + idx) < n_rows * 4) {
                cp_async16_ef(smem_u32(&sa[pos]), &a4[base4 + idx], pol);
                cp_async16_ef(smem_u32(&sb[pos]), &b4[base4 + idx], pol);
            } else {
                sa[pos] = make_float4(0.f, 0.f, 0.f, 0.f);
                sb[pos] = make_float4(0.f, 0.f, 0.f, 0.f);
            }
        }
    }
    asm volatile("cp.async.commit_group;" ::: "memory");
    asm volatile("cp.async.wait_group 0;" ::: "memory");
    __syncthreads();

    // ---- Each thread reads its own row (conflict-free via swizzle) ----
    float a[16], b[16];
    const int s = (t >> 1) & 3;
    #pragma unroll
    for (int v = 0; v < 4; ++v) {
        const int u = v ^ s;                       // physical quad holding logical quad v
        const float4 va = sa[(t << 2) | u];
        const float4 vb = sb[(t << 2) | u];
        a[v * 4 + 0] = va.x; a[v * 4 + 1] = va.y;
        a[v * 4 + 2] = va.z; a[v * 4 + 3] = va.w;
        b[v * 4 + 0] = vb.x; b[v * 4 + 1] = vb.y;
        b[v * 4 + 2] = vb.z; b[v * 4 + 3] = vb.w;
    }

    // ---- 192 straight-line FFMAs ----
    float c[16];
    #pragma unroll
    for (int k = 0; k < 16; ++k) c[k] = 0.0f;

    #pragma unroll
    for (int A = 0; A < 16; ++A) {
        #pragma unroll
        for (int B = 0; B < 16; ++B) {
            const int sg = cayley_sign(A, B);
            if (sg == 1) {
                c[A ^ B] = fmaf(a[A], b[B], c[A ^ B]);
            } else if (sg == -1) {
                c[A ^ B] = fmaf(-a[A], b[B], c[A ^ B]);
            }
        }
    }

    // ---- Write own output row into sa (own region; no pre-sync needed) ----
    #pragma unroll
    for (int v = 0; v < 4; ++v) {
        const int u = v ^ s;
        sa[(t << 2) | u] = make_float4(c[v * 4 + 0], c[v * 4 + 1],
                                       c[v * 4 + 2], c[v * 4 + 3]);
    }
    __syncthreads();

    // ---- Gather + unit-stride streaming global stores (evict-first) ----
    if (full_tile) {
        #pragma unroll
        for (int v = 0; v < 4; ++v) {
            const int idx = v * 256 + t;
            __stcs(&o4[base4 + idx], sa[swz(idx)]);
        }
    } else {
        #pragma unroll
        for (int v = 0; v < 4; ++v) {
            const int idx = v * 256 + t;
            if ((base4 + idx) < n_rows * 4)
                __stcs(&o4[base4 + idx], sa[swz(idx)]);
        }
    }
}

extern "C" void kernel_launch(void* const* d_in, const int* in_sizes, int n_in,
                              void* d_out, int out_size) {
    const float4* a4 = (const float4*)d_in[0];
    const float4* b4 = (const float4*)d_in[1];
    // d_in[2] is the Cayley tensor; values are baked in at compile time.
    float4* o4 = (float4*)d_out;

    const int n_rows = in_sizes[0] / 16;
    const int blocks = (n_rows + 255) / 256;
    gp_kernel<<<blocks, 256>>>(a4, b4, o4, n_rows);
}